// round 4
// baseline (speedup 1.0000x reference)
#include <cuda_runtime.h>
#include <cuda_bf16.h>

#define NUSER 50000
#define NN    100000        // total nodes
#define NNZE  1000000       // edges
#define EPSV  1e-12f

// ---------------- scratch (device globals) -----------------------------------
__device__ int    g_deg[NN];
__device__ int    g_rowptr[NN + 1];
__device__ int    g_cursor[NN];
__device__ int    g_tails[NNZE];      // sorted-by-head tail list
__device__ float4 g_A[NNZE];          // routing logits (sorted edge order)
__device__ float4 g_vals[NNZE];       // softmax(A)
__device__ float  g_d0[NN * 4];       // 1/sqrt(rowsum) ping
__device__ float  g_d1[NN * 4];       // 1/sqrt(rowsum) pong
__device__ float4 g_buf0[NN * 16];    // ego / hn ping
__device__ float4 g_buf1[NN * 16];    // ego / hn pong
__device__ float4 g_tt0[NN * 16];     // tanh(l2norm(xs)) for layer 0
__device__ float4 g_tt1[NN * 16];     // tanh(l2norm(xs)) for layer 1
__device__ float4 g_acc[NN * 16];     // running sum of layer embeddings

// ---------------- CSR build ---------------------------------------------------
__global__ void k_zero_deg() {
    int i = blockIdx.x * blockDim.x + threadIdx.x;
    if (i < NN) g_deg[i] = 0;
}

__global__ void k_hist(const int* __restrict__ head) {
    int e = blockIdx.x * blockDim.x + threadIdx.x;
    if (e < NNZE) atomicAdd(&g_deg[head[e]], 1);
}

__global__ void k_scan() {
    const int T = 1024;
    const int CHUNK = (NN + T - 1) / T;
    __shared__ int ssum[T];
    int t = threadIdx.x;
    int beg = t * CHUNK;
    int end = min(beg + CHUNK, NN);
    int s = 0;
    for (int i = beg; i < end; i++) s += g_deg[i];
    ssum[t] = s;
    __syncthreads();
    for (int off = 1; off < T; off <<= 1) {
        int v = 0;
        if (t >= off) v = ssum[t - off];
        __syncthreads();
        if (t >= off) ssum[t] += v;
        __syncthreads();
    }
    int run = ssum[t] - s;
    for (int i = beg; i < end; i++) {
        g_rowptr[i] = run;
        g_cursor[i] = run;
        run += g_deg[i];
    }
    if (t == T - 1) g_rowptr[NN] = ssum[T - 1];
}

__global__ void k_scatter(const int* __restrict__ head, const int* __restrict__ tail) {
    int e = blockIdx.x * blockDim.x + threadIdx.x;
    if (e >= NNZE) return;
    int pos = atomicAdd(&g_cursor[head[e]], 1);
    g_tails[pos] = tail[e];
}

// ---------------- init: ego0, acc, tt0 ----------------------------------------
__global__ void k_init(const float* __restrict__ user, const float* __restrict__ item) {
    int i = blockIdx.x * blockDim.x + threadIdx.x;   // NN*16 exact
    int n = i >> 4, c = i & 15;
    const float* src = (n < NUSER) ? (user + (size_t)n * 64 + c * 4)
                                   : (item + (size_t)(n - NUSER) * 64 + c * 4);
    float4 v = *reinterpret_cast<const float4*>(src);
    g_buf0[i] = v;
    g_acc[i]  = v;
    float ss = v.x*v.x + v.y*v.y + v.z*v.z + v.w*v.w;
    ss += __shfl_xor_sync(0xffffffffu, ss, 1);
    ss += __shfl_xor_sync(0xffffffffu, ss, 2);
    float inv = 1.f / fmaxf(sqrtf(ss), EPSV);
    g_tt0[i] = make_float4(tanhf(v.x*inv), tanhf(v.y*inv), tanhf(v.z*inv), tanhf(v.w*inv));
}

// first-iteration d: rowsum = 0.25 * degree
__global__ void k_dinit() {
    int i = blockIdx.x * blockDim.x + threadIdx.x;
    if (i >= NN * 4) return;
    int g = i >> 2;
    float s = 0.25f * (float)(g_rowptr[g + 1] - g_rowptr[g]);
    g_d0[i] = (s > 0.f) ? (1.f / sqrtf(fmaxf(s, EPSV))) : 0.f;
}

// ---------------- whole routing iteration, one WARP per node -------------------
// lanes: half = lane>>4 (edge slot), c = lane&15 (float4 chunk), f = c>>2
// loop1: h = l2norm(D A D x); loop2: scores -> A -> softmax -> vals + next d
// mode 0: write hn, scores     mode 1: + acc, tt1     mode 2: out only
__global__ void k_fused(int xsel, int dsel, int ttsel, int first, int mode,
                        float* __restrict__ out) {
    int tid  = blockIdx.x * blockDim.x + threadIdx.x;  // NN*32 exact
    int g    = tid >> 5;
    int lane = threadIdx.x & 31;
    int half = lane >> 4;
    int c    = lane & 15;
    int f    = c >> 2;

    const float4* xs = xsel ? g_buf1 : g_buf0;
    float4*       hn = xsel ? g_buf0 : g_buf1;
    const float*  dcur  = dsel ? g_d1 : g_d0;
    float*        dnext = dsel ? g_d0 : g_d1;
    const float4* tt = ttsel ? g_tt1 : g_tt0;
    const float* valsF = reinterpret_cast<const float*>(g_vals);

    int beg = g_rowptr[g], end = g_rowptr[g + 1];
    int npairs = (end - beg + 1) >> 1;

    // ---- loop 1: weighted gather (2 pairs = 4 edges in flight) ----
    float ax = 0.f, ay = 0.f, az = 0.f, aw = 0.f;
    int p = 0;
    for (; p + 1 < npairs; p += 2) {
        int j0 = beg + 2 * p + half;
        int j1 = j0 + 2;
        bool v0 = (j0 < end), v1 = (j1 < end);
        int t0 = v0 ? g_tails[j0] : 0;
        int t1 = v1 ? g_tails[j1] : 0;
        float w0 = v0 ? (first ? 0.25f : valsF[j0 * 4 + f]) : 0.f;
        float w1 = v1 ? (first ? 0.25f : valsF[j1 * 4 + f]) : 0.f;
        float s0 = w0 * dcur[t0 * 4 + f];
        float s1 = w1 * dcur[t1 * 4 + f];
        float4 x0 = xs[t0 * 16 + c];
        float4 x1 = xs[t1 * 16 + c];
        ax = fmaf(s0, x0.x, ax); ay = fmaf(s0, x0.y, ay);
        az = fmaf(s0, x0.z, az); aw = fmaf(s0, x0.w, aw);
        ax = fmaf(s1, x1.x, ax); ay = fmaf(s1, x1.y, ay);
        az = fmaf(s1, x1.z, az); aw = fmaf(s1, x1.w, aw);
    }
    if (p < npairs) {
        int j = beg + 2 * p + half;
        bool v = (j < end);
        int t = v ? g_tails[j] : 0;
        float w = v ? (first ? 0.25f : valsF[j * 4 + f]) : 0.f;
        float s = w * dcur[t * 4 + f];
        float4 x = xs[t * 16 + c];
        ax = fmaf(s, x.x, ax); ay = fmaf(s, x.y, ay);
        az = fmaf(s, x.z, az); aw = fmaf(s, x.w, aw);
    }
    // combine the two halves (chunk c lives on lanes c and c+16)
    ax += __shfl_xor_sync(0xffffffffu, ax, 16);
    ay += __shfl_xor_sync(0xffffffffu, ay, 16);
    az += __shfl_xor_sync(0xffffffffu, az, 16);
    aw += __shfl_xor_sync(0xffffffffu, aw, 16);

    float dn = dcur[g * 4 + f];
    float fx = dn * ax, fy = dn * ay, fz = dn * az, fw = dn * aw;
    float ss = fx*fx + fy*fy + fz*fz + fw*fw;
    ss += __shfl_xor_sync(0xffffffffu, ss, 1);
    ss += __shfl_xor_sync(0xffffffffu, ss, 2);
    float inv = 1.f / fmaxf(sqrtf(ss), EPSV);
    float4 h = make_float4(fx * inv, fy * inv, fz * inv, fw * inv);

    if (mode == 2) {
        if (half == 0) {
            int gid = g * 16 + c;
            float4 a = g_acc[gid];
            const float k = 1.f / 3.f;
            reinterpret_cast<float4*>(out)[gid] =
                make_float4((a.x + h.x) * k, (a.y + h.y) * k, (a.z + h.z) * k, (a.w + h.w) * k);
        }
        return;
    }
    if (half == 0) {
        int gid = g * 16 + c;
        hn[gid] = h;
        if (mode == 1) {
            float4 a = g_acc[gid];
            g_acc[gid] = make_float4(a.x + h.x, a.y + h.y, a.z + h.z, a.w + h.w);
            g_tt1[gid] = make_float4(tanhf(h.x), tanhf(h.y), tanhf(h.z), tanhf(h.w));
        }
    }

    // ---- loop 2: scores + A update + softmax + next rowsum ----
    // both halves hold identical h; each half handles one edge per step
    unsigned hbase = half << 4;                 // 0 or 16
    float rs0 = 0.f, rs1 = 0.f, rs2 = 0.f, rs3 = 0.f;
    p = 0;
    for (; p + 1 < npairs; p += 2) {
        int j0 = beg + 2 * p + half;
        int j1 = j0 + 2;
        bool v0 = (j0 < end), v1 = (j1 < end);
        int t0 = v0 ? g_tails[j0] : 0;
        int t1 = v1 ? g_tails[j1] : 0;
        float4 b0 = tt[t0 * 16 + c];
        float4 b1 = tt[t1 * 16 + c];
        float p0 = h.x*b0.x + h.y*b0.y + h.z*b0.z + h.w*b0.w;
        float p1 = h.x*b1.x + h.y*b1.y + h.z*b1.z + h.w*b1.w;
        p0 += __shfl_xor_sync(0xffffffffu, p0, 1);
        p0 += __shfl_xor_sync(0xffffffffu, p0, 2);
        p1 += __shfl_xor_sync(0xffffffffu, p1, 1);
        p1 += __shfl_xor_sync(0xffffffffu, p1, 2);
        float a0s0 = __shfl_sync(0xffffffffu, p0, hbase + 0);
        float a0s1 = __shfl_sync(0xffffffffu, p0, hbase + 4);
        float a0s2 = __shfl_sync(0xffffffffu, p0, hbase + 8);
        float a0s3 = __shfl_sync(0xffffffffu, p0, hbase + 12);
        float a1s0 = __shfl_sync(0xffffffffu, p1, hbase + 0);
        float a1s1 = __shfl_sync(0xffffffffu, p1, hbase + 4);
        float a1s2 = __shfl_sync(0xffffffffu, p1, hbase + 8);
        float a1s3 = __shfl_sync(0xffffffffu, p1, hbase + 12);
        if (c == 0 && v0) {
            float4 A = first ? make_float4(1.f, 1.f, 1.f, 1.f) : g_A[j0];
            A.x += a0s0; A.y += a0s1; A.z += a0s2; A.w += a0s3;
            g_A[j0] = A;
            float m = fmaxf(fmaxf(A.x, A.y), fmaxf(A.z, A.w));
            float e0 = __expf(A.x - m), e1 = __expf(A.y - m);
            float e2 = __expf(A.z - m), e3 = __expf(A.w - m);
            float r = 1.f / (e0 + e1 + e2 + e3);
            float4 v = make_float4(e0 * r, e1 * r, e2 * r, e3 * r);
            g_vals[j0] = v;
            rs0 += v.x; rs1 += v.y; rs2 += v.z; rs3 += v.w;
        }
        if (c == 0 && v1) {
            float4 A = first ? make_float4(1.f, 1.f, 1.f, 1.f) : g_A[j1];
            A.x += a1s0; A.y += a1s1; A.z += a1s2; A.w += a1s3;
            g_A[j1] = A;
            float m = fmaxf(fmaxf(A.x, A.y), fmaxf(A.z, A.w));
            float e0 = __expf(A.x - m), e1 = __expf(A.y - m);
            float e2 = __expf(A.z - m), e3 = __expf(A.w - m);
            float r = 1.f / (e0 + e1 + e2 + e3);
            float4 v = make_float4(e0 * r, e1 * r, e2 * r, e3 * r);
            g_vals[j1] = v;
            rs0 += v.x; rs1 += v.y; rs2 += v.z; rs3 += v.w;
        }
    }
    if (p < npairs) {
        int j = beg + 2 * p + half;
        bool v = (j < end);
        int t = v ? g_tails[j] : 0;
        float4 b = tt[t * 16 + c];
        float pp = h.x*b.x + h.y*b.y + h.z*b.z + h.w*b.w;
        pp += __shfl_xor_sync(0xffffffffu, pp, 1);
        pp += __shfl_xor_sync(0xffffffffu, pp, 2);
        float s0 = __shfl_sync(0xffffffffu, pp, hbase + 0);
        float s1 = __shfl_sync(0xffffffffu, pp, hbase + 4);
        float s2 = __shfl_sync(0xffffffffu, pp, hbase + 8);
        float s3 = __shfl_sync(0xffffffffu, pp, hbase + 12);
        if (c == 0 && v) {
            float4 A = first ? make_float4(1.f, 1.f, 1.f, 1.f) : g_A[j];
            A.x += s0; A.y += s1; A.z += s2; A.w += s3;
            g_A[j] = A;
            float m = fmaxf(fmaxf(A.x, A.y), fmaxf(A.z, A.w));
            float e0 = __expf(A.x - m), e1 = __expf(A.y - m);
            float e2 = __expf(A.z - m), e3 = __expf(A.w - m);
            float r = 1.f / (e0 + e1 + e2 + e3);
            float4 vv = make_float4(e0 * r, e1 * r, e2 * r, e3 * r);
            g_vals[j] = vv;
            rs0 += vv.x; rs1 += vv.y; rs2 += vv.z; rs3 += vv.w;
        }
    }
    // combine rowsums from the two halves (held on lanes 0 and 16)
    rs0 += __shfl_xor_sync(0xffffffffu, rs0, 16);
    rs1 += __shfl_xor_sync(0xffffffffu, rs1, 16);
    rs2 += __shfl_xor_sync(0xffffffffu, rs2, 16);
    rs3 += __shfl_xor_sync(0xffffffffu, rs3, 16);
    if (lane == 0) {
        dnext[g * 4 + 0] = (rs0 > 0.f) ? (1.f / sqrtf(fmaxf(rs0, EPSV))) : 0.f;
        dnext[g * 4 + 1] = (rs1 > 0.f) ? (1.f / sqrtf(fmaxf(rs1, EPSV))) : 0.f;
        dnext[g * 4 + 2] = (rs2 > 0.f) ? (1.f / sqrtf(fmaxf(rs2, EPSV))) : 0.f;
        dnext[g * 4 + 3] = (rs3 > 0.f) ? (1.f / sqrtf(fmaxf(rs3, EPSV))) : 0.f;
    }
}

// ---------------- launch -------------------------------------------------------
extern "C" void kernel_launch(void* const* d_in, const int* in_sizes, int n_in,
                              void* d_out, int out_size) {
    const float* user = (const float*)d_in[0];
    const float* item = (const float*)d_in[1];
    const int*   head = (const int*)d_in[2];
    const int*   tail = (const int*)d_in[3];
    float* out = (float*)d_out;

    const int TB = 256;
    const int gN   = (NN + TB - 1) / TB;
    const int gN4  = (NN * 4 + TB - 1) / TB;
    const int gN16 = (NN * 16) / TB;        // exact
    const int gN32 = (NN * 32) / TB;        // exact: warp per node
    const int gE   = (NNZE + TB - 1) / TB;

    // CSR build
    k_zero_deg<<<gN, TB>>>();
    k_hist<<<gE, TB>>>(head);
    k_scan<<<1, 1024>>>();
    k_scatter<<<gE, TB>>>(head, tail);

    // ego0 + acc + tt0; d for iteration 1
    k_init<<<gN16, TB>>>(user, item);
    k_dinit<<<gN4, TB>>>();

    //            xsel dsel ttsel first mode
    k_fused<<<gN32, TB>>>(0, 0, 0, 1, 0, out);   // layer0 iter1
    k_fused<<<gN32, TB>>>(0, 1, 0, 0, 1, out);   // layer0 iter2: acc+, tt1
    k_fused<<<gN32, TB>>>(1, 0, 1, 0, 0, out);   // layer1 iter1
    k_fused<<<gN32, TB>>>(1, 1, 1, 0, 2, out);   // layer1 iter2: out
}

// round 5
// speedup vs baseline: 1.2108x; 1.2108x over previous
#include <cuda_runtime.h>
#include <cuda_fp16.h>

#define NUSER 50000
#define NN    100000        // total nodes
#define NNZE  1000000       // edges
#define EPSV  1e-12f

// ---------------- scratch (device globals) -----------------------------------
__device__ int    g_deg[NN];
__device__ int    g_rowptr[NN + 1];
__device__ int    g_cursor[NN];
__device__ int    g_tails[NNZE];      // sorted-by-head tail list
__device__ float4 g_A[NNZE];          // routing logits (sorted edge order)
__device__ float4 g_vals[NNZE];       // softmax(A)
__device__ float  g_d0[NN * 4];       // 1/sqrt(rowsum) ping
__device__ float  g_d1[NN * 4];       // 1/sqrt(rowsum) pong
__device__ uint2  g_h0[NN * 16];      // ego / hn ping  (fp16 x4 per chunk)
__device__ uint2  g_h1[NN * 16];      // ego / hn pong  (fp16 x4)
__device__ uint2  g_tth0[NN * 16];    // tanh(l2norm(xs)) layer 0 (fp16 x4)
__device__ uint2  g_tth1[NN * 16];    // tanh(l2norm(xs)) layer 1 (fp16 x4)
__device__ float4 g_acc[NN * 16];     // running sum of layer embeddings (fp32)

// fp16x4 <-> float4 helpers
__device__ __forceinline__ float4 ld_h4(const uint2* p, int i) {
    uint2 u = __ldg(&p[i]);
    __half2 a = *reinterpret_cast<__half2*>(&u.x);
    __half2 b = *reinterpret_cast<__half2*>(&u.y);
    float2 fa = __half22float2(a), fb = __half22float2(b);
    return make_float4(fa.x, fa.y, fb.x, fb.y);
}
__device__ __forceinline__ uint2 st_h4(float4 v) {
    __half2 a = __floats2half2_rn(v.x, v.y);
    __half2 b = __floats2half2_rn(v.z, v.w);
    uint2 u;
    u.x = *reinterpret_cast<unsigned*>(&a);
    u.y = *reinterpret_cast<unsigned*>(&b);
    return u;
}

// ---------------- CSR build ---------------------------------------------------
__global__ void k_zero_deg() {
    int i = blockIdx.x * blockDim.x + threadIdx.x;
    if (i < NN) g_deg[i] = 0;
}

__global__ void k_hist(const int* __restrict__ head) {
    int e = blockIdx.x * blockDim.x + threadIdx.x;
    if (e < NNZE) atomicAdd(&g_deg[head[e]], 1);
}

__global__ void k_scan() {
    const int T = 1024;
    const int CHUNK = (NN + T - 1) / T;
    __shared__ int ssum[T];
    int t = threadIdx.x;
    int beg = t * CHUNK;
    int end = min(beg + CHUNK, NN);
    int s = 0;
    for (int i = beg; i < end; i++) s += g_deg[i];
    ssum[t] = s;
    __syncthreads();
    for (int off = 1; off < T; off <<= 1) {
        int v = 0;
        if (t >= off) v = ssum[t - off];
        __syncthreads();
        if (t >= off) ssum[t] += v;
        __syncthreads();
    }
    int run = ssum[t] - s;
    for (int i = beg; i < end; i++) {
        g_rowptr[i] = run;
        g_cursor[i] = run;
        run += g_deg[i];
    }
    if (t == T - 1) g_rowptr[NN] = ssum[T - 1];
}

__global__ void k_scatter(const int* __restrict__ head, const int* __restrict__ tail) {
    int e = blockIdx.x * blockDim.x + threadIdx.x;
    if (e >= NNZE) return;
    int pos = atomicAdd(&g_cursor[head[e]], 1);
    g_tails[pos] = tail[e];
}

// ---------------- init: ego0(fp16), acc(fp32), tt0(fp16) ----------------------
__global__ void k_init(const float* __restrict__ user, const float* __restrict__ item) {
    int i = blockIdx.x * blockDim.x + threadIdx.x;   // NN*16 exact
    int n = i >> 4, c = i & 15;
    const float* src = (n < NUSER) ? (user + (size_t)n * 64 + c * 4)
                                   : (item + (size_t)(n - NUSER) * 64 + c * 4);
    float4 v = *reinterpret_cast<const float4*>(src);
    g_h0[i] = st_h4(v);
    g_acc[i] = v;
    float ss = v.x*v.x + v.y*v.y + v.z*v.z + v.w*v.w;
    ss += __shfl_xor_sync(0xffffffffu, ss, 1);
    ss += __shfl_xor_sync(0xffffffffu, ss, 2);
    float inv = 1.f / fmaxf(sqrtf(ss), EPSV);
    g_tth0[i] = st_h4(make_float4(tanhf(v.x*inv), tanhf(v.y*inv),
                                  tanhf(v.z*inv), tanhf(v.w*inv)));
}

// first-iteration d: rowsum = 0.25 * degree
__global__ void k_dinit() {
    int i = blockIdx.x * blockDim.x + threadIdx.x;
    if (i >= NN * 4) return;
    int g = i >> 2;
    float s = 0.25f * (float)(g_rowptr[g + 1] - g_rowptr[g]);
    g_d0[i] = (s > 0.f) ? (1.f / sqrtf(fmaxf(s, EPSV))) : 0.f;
}

// ---------------- whole routing iteration (16 lanes per node) -----------------
// mode 0: write hn, scores    mode 1: + acc, tt1    mode 2: out only
__global__ void k_fused(int xsel, int dsel, int ttsel, int first, int mode,
                        float* __restrict__ out) {
    int gid = blockIdx.x * blockDim.x + threadIdx.x;   // NN*16 exact
    int g = gid >> 4, c = gid & 15, f = c >> 2;
    const uint2* xs = xsel ? g_h1 : g_h0;
    uint2*       hn = xsel ? g_h0 : g_h1;
    const float*  dcur  = dsel ? g_d1 : g_d0;
    float*        dnext = dsel ? g_d0 : g_d1;
    const uint2* tt = ttsel ? g_tth1 : g_tth0;
    const float* valsF = reinterpret_cast<const float*>(g_vals);
    int beg = g_rowptr[g], end = g_rowptr[g + 1];

    // ---- loop 1: h = l2norm(D A D x) per factor ----
    float ax = 0.f, ay = 0.f, az = 0.f, aw = 0.f;
    int j = beg;
    for (; j + 1 < end; j += 2) {
        int t0 = g_tails[j], t1 = g_tails[j + 1];
        float w0 = first ? 0.25f : valsF[j * 4 + f];
        float w1 = first ? 0.25f : valsF[(j + 1) * 4 + f];
        float s0 = w0 * dcur[t0 * 4 + f];
        float s1 = w1 * dcur[t1 * 4 + f];
        float4 x0 = ld_h4(xs, t0 * 16 + c);
        float4 x1 = ld_h4(xs, t1 * 16 + c);
        ax = fmaf(s0, x0.x, ax); ay = fmaf(s0, x0.y, ay);
        az = fmaf(s0, x0.z, az); aw = fmaf(s0, x0.w, aw);
        ax = fmaf(s1, x1.x, ax); ay = fmaf(s1, x1.y, ay);
        az = fmaf(s1, x1.z, az); aw = fmaf(s1, x1.w, aw);
    }
    if (j < end) {
        int t = g_tails[j];
        float w = first ? 0.25f : valsF[j * 4 + f];
        float s = w * dcur[t * 4 + f];
        float4 x = ld_h4(xs, t * 16 + c);
        ax = fmaf(s, x.x, ax); ay = fmaf(s, x.y, ay);
        az = fmaf(s, x.z, az); aw = fmaf(s, x.w, aw);
    }
    float dn = dcur[g * 4 + f];
    float fx = dn * ax, fy = dn * ay, fz = dn * az, fw = dn * aw;
    float ss = fx*fx + fy*fy + fz*fz + fw*fw;
    ss += __shfl_xor_sync(0xffffffffu, ss, 1);
    ss += __shfl_xor_sync(0xffffffffu, ss, 2);
    float inv = 1.f / fmaxf(sqrtf(ss), EPSV);
    float4 h = make_float4(fx * inv, fy * inv, fz * inv, fw * inv);

    if (mode == 2) {
        float4 a = g_acc[gid];
        const float k = 1.f / 3.f;
        reinterpret_cast<float4*>(out)[gid] =
            make_float4((a.x + h.x) * k, (a.y + h.y) * k, (a.z + h.z) * k, (a.w + h.w) * k);
        return;
    }
    hn[gid] = st_h4(h);
    if (mode == 1) {
        float4 a = g_acc[gid];
        g_acc[gid] = make_float4(a.x + h.x, a.y + h.y, a.z + h.z, a.w + h.w);
        g_tth1[gid] = st_h4(make_float4(tanhf(h.x), tanhf(h.y), tanhf(h.z), tanhf(h.w)));
    }

    // ---- loop 2: scores + A update + softmax + next rowsum ----
    // 16-lane group; masks restricted to group (rows in same warp differ in length)
    unsigned gbase = threadIdx.x & 16;          // 0 or 16
    unsigned gmask = 0xFFFFu << gbase;
    float rs0 = 0.f, rs1 = 0.f, rs2 = 0.f, rs3 = 0.f;
    j = beg;
    for (; j + 1 < end; j += 2) {
        int t0 = g_tails[j], t1 = g_tails[j + 1];
        float4 b0 = ld_h4(tt, t0 * 16 + c);
        float4 b1 = ld_h4(tt, t1 * 16 + c);
        float p0 = h.x*b0.x + h.y*b0.y + h.z*b0.z + h.w*b0.w;
        float p1 = h.x*b1.x + h.y*b1.y + h.z*b1.z + h.w*b1.w;
        p0 += __shfl_xor_sync(gmask, p0, 1);
        p0 += __shfl_xor_sync(gmask, p0, 2);
        p1 += __shfl_xor_sync(gmask, p1, 1);
        p1 += __shfl_xor_sync(gmask, p1, 2);
        float a0 = __shfl_sync(gmask, p0, gbase + 0);
        float a1 = __shfl_sync(gmask, p0, gbase + 4);
        float a2 = __shfl_sync(gmask, p0, gbase + 8);
        float a3 = __shfl_sync(gmask, p0, gbase + 12);
        float b0s = __shfl_sync(gmask, p1, gbase + 0);
        float b1s = __shfl_sync(gmask, p1, gbase + 4);
        float b2s = __shfl_sync(gmask, p1, gbase + 8);
        float b3s = __shfl_sync(gmask, p1, gbase + 12);
        if (c == 0) {
            float4 A = first ? make_float4(1.f, 1.f, 1.f, 1.f) : g_A[j];
            A.x += a0; A.y += a1; A.z += a2; A.w += a3;
            g_A[j] = A;
            float m = fmaxf(fmaxf(A.x, A.y), fmaxf(A.z, A.w));
            float e0 = __expf(A.x - m), e1 = __expf(A.y - m);
            float e2 = __expf(A.z - m), e3 = __expf(A.w - m);
            float r = 1.f / (e0 + e1 + e2 + e3);
            float4 v = make_float4(e0 * r, e1 * r, e2 * r, e3 * r);
            g_vals[j] = v;
            rs0 += v.x; rs1 += v.y; rs2 += v.z; rs3 += v.w;

            float4 B = first ? make_float4(1.f, 1.f, 1.f, 1.f) : g_A[j + 1];
            B.x += b0s; B.y += b1s; B.z += b2s; B.w += b3s;
            g_A[j + 1] = B;
            float m2 = fmaxf(fmaxf(B.x, B.y), fmaxf(B.z, B.w));
            float f0 = __expf(B.x - m2), f1 = __expf(B.y - m2);
            float f2 = __expf(B.z - m2), f3 = __expf(B.w - m2);
            float r2 = 1.f / (f0 + f1 + f2 + f3);
            float4 v2 = make_float4(f0 * r2, f1 * r2, f2 * r2, f3 * r2);
            g_vals[j + 1] = v2;
            rs0 += v2.x; rs1 += v2.y; rs2 += v2.z; rs3 += v2.w;
        }
    }
    if (j < end) {
        int t = g_tails[j];
        float4 b = ld_h4(tt, t * 16 + c);
        float p = h.x*b.x + h.y*b.y + h.z*b.z + h.w*b.w;
        p += __shfl_xor_sync(gmask, p, 1);
        p += __shfl_xor_sync(gmask, p, 2);
        float s0 = __shfl_sync(gmask, p, gbase + 0);
        float s1 = __shfl_sync(gmask, p, gbase + 4);
        float s2 = __shfl_sync(gmask, p, gbase + 8);
        float s3 = __shfl_sync(gmask, p, gbase + 12);
        if (c == 0) {
            float4 A = first ? make_float4(1.f, 1.f, 1.f, 1.f) : g_A[j];
            A.x += s0; A.y += s1; A.z += s2; A.w += s3;
            g_A[j] = A;
            float m = fmaxf(fmaxf(A.x, A.y), fmaxf(A.z, A.w));
            float e0 = __expf(A.x - m), e1 = __expf(A.y - m);
            float e2 = __expf(A.z - m), e3 = __expf(A.w - m);
            float r = 1.f / (e0 + e1 + e2 + e3);
            float4 v = make_float4(e0 * r, e1 * r, e2 * r, e3 * r);
            g_vals[j] = v;
            rs0 += v.x; rs1 += v.y; rs2 += v.z; rs3 += v.w;
        }
    }
    if (c == 0) {
        dnext[g * 4 + 0] = (rs0 > 0.f) ? (1.f / sqrtf(fmaxf(rs0, EPSV))) : 0.f;
        dnext[g * 4 + 1] = (rs1 > 0.f) ? (1.f / sqrtf(fmaxf(rs1, EPSV))) : 0.f;
        dnext[g * 4 + 2] = (rs2 > 0.f) ? (1.f / sqrtf(fmaxf(rs2, EPSV))) : 0.f;
        dnext[g * 4 + 3] = (rs3 > 0.f) ? (1.f / sqrtf(fmaxf(rs3, EPSV))) : 0.f;
    }
}

// ---------------- launch -------------------------------------------------------
extern "C" void kernel_launch(void* const* d_in, const int* in_sizes, int n_in,
                              void* d_out, int out_size) {
    const float* user = (const float*)d_in[0];
    const float* item = (const float*)d_in[1];
    const int*   head = (const int*)d_in[2];
    const int*   tail = (const int*)d_in[3];
    float* out = (float*)d_out;

    const int TB = 256;
    const int gN   = (NN + TB - 1) / TB;
    const int gN4  = (NN * 4 + TB - 1) / TB;
    const int gN16 = (NN * 16) / TB;        // exact
    const int gE   = (NNZE + TB - 1) / TB;

    // CSR build
    k_zero_deg<<<gN, TB>>>();
    k_hist<<<gE, TB>>>(head);
    k_scan<<<1, 1024>>>();
    k_scatter<<<gE, TB>>>(head, tail);

    // ego0 + acc + tt0; d for iteration 1
    k_init<<<gN16, TB>>>(user, item);
    k_dinit<<<gN4, TB>>>();

    //            xsel dsel ttsel first mode
    k_fused<<<gN16, TB>>>(0, 0, 0, 1, 0, out);   // layer0 iter1
    k_fused<<<gN16, TB>>>(0, 1, 0, 0, 1, out);   // layer0 iter2: acc+, tt1
    k_fused<<<gN16, TB>>>(1, 0, 1, 0, 0, out);   // layer1 iter1
    k_fused<<<gN16, TB>>>(1, 1, 1, 0, 2, out);   // layer1 iter2: out
}

// round 6
// speedup vs baseline: 1.3286x; 1.0973x over previous
#include <cuda_runtime.h>
#include <cuda_fp16.h>

#define NUSER 50000
#define NN    100000        // total nodes
#define NNZE  1000000       // edges
#define EPSV  1e-12f

// ---------------- scratch (device globals) -----------------------------------
__device__ int    g_deg[NN];
__device__ int    g_rowptr[NN + 1];
__device__ int    g_cursor[NN];
__device__ int    g_tails[NNZE];      // sorted-by-head tail list
__device__ float  g_A[NNZE * 4];      // routing logits (sorted edge order)
__device__ float  g_vals[NNZE * 4];   // softmax(A)
__device__ float  g_d0[NN * 4];       // 1/sqrt(rowsum) ping
__device__ float  g_d1[NN * 4];       // 1/sqrt(rowsum) pong
__device__ uint2  g_h0[NN * 16];      // ego / hn ping  (fp16 x4 per chunk)
__device__ uint2  g_h1[NN * 16];      // ego / hn pong  (fp16 x4)
__device__ uint2  g_tth0[NN * 16];    // tanh(l2norm(xs)) layer 0 (fp16 x4)
__device__ uint2  g_tth1[NN * 16];    // tanh(l2norm(xs)) layer 1 (fp16 x4)
__device__ float4 g_acc[NN * 16];     // running sum of layer embeddings (fp32)

// fp16x4 <-> float4 helpers
__device__ __forceinline__ float4 ld_h4(const uint2* p, int i) {
    uint2 u = __ldg(&p[i]);
    __half2 a = *reinterpret_cast<__half2*>(&u.x);
    __half2 b = *reinterpret_cast<__half2*>(&u.y);
    float2 fa = __half22float2(a), fb = __half22float2(b);
    return make_float4(fa.x, fa.y, fb.x, fb.y);
}
__device__ __forceinline__ uint2 st_h4(float4 v) {
    __half2 a = __floats2half2_rn(v.x, v.y);
    __half2 b = __floats2half2_rn(v.z, v.w);
    uint2 u;
    u.x = *reinterpret_cast<unsigned*>(&a);
    u.y = *reinterpret_cast<unsigned*>(&b);
    return u;
}

// ---------------- CSR build ---------------------------------------------------
__global__ void k_zero_deg() {
    int i = blockIdx.x * blockDim.x + threadIdx.x;
    if (i < NN) g_deg[i] = 0;
}

__global__ void k_hist(const int* __restrict__ head) {
    int e = blockIdx.x * blockDim.x + threadIdx.x;
    if (e < NNZE) atomicAdd(&g_deg[head[e]], 1);
}

__global__ void k_scan() {
    const int T = 1024;
    const int CHUNK = (NN + T - 1) / T;
    __shared__ int ssum[T];
    int t = threadIdx.x;
    int beg = t * CHUNK;
    int end = min(beg + CHUNK, NN);
    int s = 0;
    for (int i = beg; i < end; i++) s += g_deg[i];
    ssum[t] = s;
    __syncthreads();
    for (int off = 1; off < T; off <<= 1) {
        int v = 0;
        if (t >= off) v = ssum[t - off];
        __syncthreads();
        if (t >= off) ssum[t] += v;
        __syncthreads();
    }
    int run = ssum[t] - s;
    for (int i = beg; i < end; i++) {
        g_rowptr[i] = run;
        g_cursor[i] = run;
        run += g_deg[i];
    }
    if (t == T - 1) g_rowptr[NN] = ssum[T - 1];
}

__global__ void k_scatter(const int* __restrict__ head, const int* __restrict__ tail) {
    int e = blockIdx.x * blockDim.x + threadIdx.x;
    if (e >= NNZE) return;
    int pos = atomicAdd(&g_cursor[head[e]], 1);
    g_tails[pos] = tail[e];
}

// ---------------- init: ego0(fp16), acc(fp32), tt0(fp16), d0 ------------------
// runs AFTER k_scan (needs rowptr for the fused d-init)
__global__ void k_init(const float* __restrict__ user, const float* __restrict__ item) {
    int i = blockIdx.x * blockDim.x + threadIdx.x;   // NN*16 exact
    int n = i >> 4, c = i & 15;
    const float* src = (n < NUSER) ? (user + (size_t)n * 64 + c * 4)
                                   : (item + (size_t)(n - NUSER) * 64 + c * 4);
    float4 v = *reinterpret_cast<const float4*>(src);
    g_h0[i] = st_h4(v);
    g_acc[i] = v;
    float ss = v.x*v.x + v.y*v.y + v.z*v.z + v.w*v.w;
    ss += __shfl_xor_sync(0xffffffffu, ss, 1);
    ss += __shfl_xor_sync(0xffffffffu, ss, 2);
    float inv = 1.f / fmaxf(sqrtf(ss), EPSV);
    g_tth0[i] = st_h4(make_float4(tanhf(v.x*inv), tanhf(v.y*inv),
                                  tanhf(v.z*inv), tanhf(v.w*inv)));
    if (c < 4) {
        float s = 0.25f * (float)(g_rowptr[n + 1] - g_rowptr[n]);
        g_d0[n * 4 + c] = (s > 0.f) ? (1.f / sqrtf(fmaxf(s, EPSV))) : 0.f;
    }
}

// ---------------- whole routing iteration (16 lanes per node) -----------------
// FACTOR-MAJOR lane map: lane c -> factor fl=c&3, subchunk s=c>>2, chunk=fl*4+s
// mode 0: write hn, scores    mode 1: + acc, tt1    mode 2: out only
__global__ void k_fused(int xsel, int dsel, int ttsel, int first, int mode,
                        float* __restrict__ out) {
    int gid = blockIdx.x * blockDim.x + threadIdx.x;   // NN*16 exact
    int g  = gid >> 4, c = gid & 15;
    int fl = c & 3, s = c >> 2;
    int chunk = fl * 4 + s;
    int idx = g * 16 + chunk;

    const uint2* xs = xsel ? g_h1 : g_h0;
    uint2*       hn = xsel ? g_h0 : g_h1;
    const float* dcur  = dsel ? g_d1 : g_d0;
    float*       dnext = dsel ? g_d0 : g_d1;
    const uint2* tt = ttsel ? g_tth1 : g_tth0;

    unsigned gbase = threadIdx.x & 16;          // 0 or 16
    unsigned gmask = 0xFFFFu << gbase;          // 16-lane group
    unsigned smask = 0xFu << gbase;             // the 4 s==0 lanes of the group

    int beg = g_rowptr[g], end = g_rowptr[g + 1];

    // ---- loop 1: h = l2norm(D A D x) per factor ----
    float ax = 0.f, ay = 0.f, az = 0.f, aw = 0.f;
    int j = beg;
    for (; j + 1 < end; j += 2) {
        int t0 = g_tails[j], t1 = g_tails[j + 1];
        float w0 = first ? 0.25f : g_vals[j * 4 + fl];
        float w1 = first ? 0.25f : g_vals[(j + 1) * 4 + fl];
        float s0 = w0 * dcur[t0 * 4 + fl];
        float s1 = w1 * dcur[t1 * 4 + fl];
        float4 x0 = ld_h4(xs, t0 * 16 + chunk);
        float4 x1 = ld_h4(xs, t1 * 16 + chunk);
        ax = fmaf(s0, x0.x, ax); ay = fmaf(s0, x0.y, ay);
        az = fmaf(s0, x0.z, az); aw = fmaf(s0, x0.w, aw);
        ax = fmaf(s1, x1.x, ax); ay = fmaf(s1, x1.y, ay);
        az = fmaf(s1, x1.z, az); aw = fmaf(s1, x1.w, aw);
    }
    if (j < end) {
        int t = g_tails[j];
        float w = first ? 0.25f : g_vals[j * 4 + fl];
        float sc = w * dcur[t * 4 + fl];
        float4 x = ld_h4(xs, t * 16 + chunk);
        ax = fmaf(sc, x.x, ax); ay = fmaf(sc, x.y, ay);
        az = fmaf(sc, x.z, az); aw = fmaf(sc, x.w, aw);
    }
    float dn = dcur[g * 4 + fl];
    float fx = dn * ax, fy = dn * ay, fz = dn * az, fw = dn * aw;
    float ss = fx*fx + fy*fy + fz*fz + fw*fw;
    ss += __shfl_xor_sync(gmask, ss, 4);        // reduce over subchunks
    ss += __shfl_xor_sync(gmask, ss, 8);
    float inv = 1.f / fmaxf(sqrtf(ss), EPSV);
    float4 h = make_float4(fx * inv, fy * inv, fz * inv, fw * inv);

    if (mode == 2) {
        float4 a = g_acc[idx];
        const float k = 1.f / 3.f;
        reinterpret_cast<float4*>(out)[idx] =
            make_float4((a.x + h.x) * k, (a.y + h.y) * k, (a.z + h.z) * k, (a.w + h.w) * k);
        return;
    }
    hn[idx] = st_h4(h);
    if (mode == 1) {
        float4 a = g_acc[idx];
        g_acc[idx] = make_float4(a.x + h.x, a.y + h.y, a.z + h.z, a.w + h.w);
        g_tth1[idx] = st_h4(make_float4(tanhf(h.x), tanhf(h.y), tanhf(h.z), tanhf(h.w)));
    }

    // ---- loop 2: scores + A update + softmax + next rowsum ----
    // after xor4/xor8 every lane holds its factor's score; the 4 s==0 lanes
    // do the per-edge A update + softmax in PARALLEL across factors.
    float rs = 0.f;                              // per-factor rowsum (s==0 lanes)
    j = beg;
    for (; j + 1 < end; j += 2) {
        int t0 = g_tails[j], t1 = g_tails[j + 1];
        float4 b0 = ld_h4(tt, t0 * 16 + chunk);
        float4 b1 = ld_h4(tt, t1 * 16 + chunk);
        float p0 = h.x*b0.x + h.y*b0.y + h.z*b0.z + h.w*b0.w;
        float p1 = h.x*b1.x + h.y*b1.y + h.z*b1.z + h.w*b1.w;
        p0 += __shfl_xor_sync(gmask, p0, 4);
        p0 += __shfl_xor_sync(gmask, p0, 8);
        p1 += __shfl_xor_sync(gmask, p1, 4);
        p1 += __shfl_xor_sync(gmask, p1, 8);
        if (s == 0) {
            // edge j
            float A0 = (first ? 1.f : g_A[j * 4 + fl]) + p0;
            g_A[j * 4 + fl] = A0;
            float m0 = A0;
            m0 = fmaxf(m0, __shfl_xor_sync(smask, m0, 1));
            m0 = fmaxf(m0, __shfl_xor_sync(smask, m0, 2));
            float e0 = __expf(A0 - m0);
            float sum0 = e0;
            sum0 += __shfl_xor_sync(smask, sum0, 1);
            sum0 += __shfl_xor_sync(smask, sum0, 2);
            float v0 = e0 / sum0;
            g_vals[j * 4 + fl] = v0;
            rs += v0;
            // edge j+1
            float A1 = (first ? 1.f : g_A[(j + 1) * 4 + fl]) + p1;
            g_A[(j + 1) * 4 + fl] = A1;
            float m1 = A1;
            m1 = fmaxf(m1, __shfl_xor_sync(smask, m1, 1));
            m1 = fmaxf(m1, __shfl_xor_sync(smask, m1, 2));
            float e1 = __expf(A1 - m1);
            float sum1 = e1;
            sum1 += __shfl_xor_sync(smask, sum1, 1);
            sum1 += __shfl_xor_sync(smask, sum1, 2);
            float v1 = e1 / sum1;
            g_vals[(j + 1) * 4 + fl] = v1;
            rs += v1;
        }
    }
    if (j < end) {
        int t = g_tails[j];
        float4 b = ld_h4(tt, t * 16 + chunk);
        float p = h.x*b.x + h.y*b.y + h.z*b.z + h.w*b.w;
        p += __shfl_xor_sync(gmask, p, 4);
        p += __shfl_xor_sync(gmask, p, 8);
        if (s == 0) {
            float A0 = (first ? 1.f : g_A[j * 4 + fl]) + p;
            g_A[j * 4 + fl] = A0;
            float m0 = A0;
            m0 = fmaxf(m0, __shfl_xor_sync(smask, m0, 1));
            m0 = fmaxf(m0, __shfl_xor_sync(smask, m0, 2));
            float e0 = __expf(A0 - m0);
            float sum0 = e0;
            sum0 += __shfl_xor_sync(smask, sum0, 1);
            sum0 += __shfl_xor_sync(smask, sum0, 2);
            float v0 = e0 / sum0;
            g_vals[j * 4 + fl] = v0;
            rs += v0;
        }
    }
    if (s == 0) {
        dnext[g * 4 + fl] = (rs > 0.f) ? (1.f / sqrtf(fmaxf(rs, EPSV))) : 0.f;
    }
}

// ---------------- launch -------------------------------------------------------
extern "C" void kernel_launch(void* const* d_in, const int* in_sizes, int n_in,
                              void* d_out, int out_size) {
    const float* user = (const float*)d_in[0];
    const float* item = (const float*)d_in[1];
    const int*   head = (const int*)d_in[2];
    const int*   tail = (const int*)d_in[3];
    float* out = (float*)d_out;

    const int TB = 256;
    const int gN   = (NN + TB - 1) / TB;
    const int gN16 = (NN * 16) / TB;        // exact
    const int gE   = (NNZE + TB - 1) / TB;

    // CSR build
    k_zero_deg<<<gN, TB>>>();
    k_hist<<<gE, TB>>>(head);
    k_scan<<<1, 1024>>>();
    k_scatter<<<gE, TB>>>(head, tail);

    // ego0 + acc + tt0 + first-iteration d (needs rowptr)
    k_init<<<gN16, TB>>>(user, item);

    //            xsel dsel ttsel first mode
    k_fused<<<gN16, TB>>>(0, 0, 0, 1, 0, out);   // layer0 iter1
    k_fused<<<gN16, TB>>>(0, 1, 0, 0, 1, out);   // layer0 iter2: acc+, tt1
    k_fused<<<gN16, TB>>>(1, 0, 1, 0, 0, out);   // layer1 iter1
    k_fused<<<gN16, TB>>>(1, 1, 1, 0, 2, out);   // layer1 iter2: out
}

// round 8
// speedup vs baseline: 1.5409x; 1.1598x over previous
#include <cuda_runtime.h>
#include <cuda_fp16.h>

#define NUSER 50000
#define NN    100000        // total nodes
#define NNZE  1000000       // edges
#define EPSV  1e-12f

// ---------------- scratch (device globals) -----------------------------------
__device__ int    g_deg[NN];
__device__ int    g_rowptr[NN + 1];
__device__ int    g_cursor[NN];
__device__ int    g_tails[NNZE];      // sorted-by-head tail list
__device__ float  g_A[NNZE * 4];      // routing logits (sorted edge order)
__device__ float  g_vals[NNZE * 4];   // softmax(A)
__device__ float  g_d0[NN * 4];       // 1/sqrt(rowsum) ping
__device__ float  g_d1[NN * 4];       // 1/sqrt(rowsum) pong
__device__ uint2  g_h0[NN * 16];      // ego / hn ping  (fp16 x4 per chunk)
__device__ uint2  g_h1[NN * 16];      // ego / hn pong  (fp16 x4)
__device__ uint4  g_tth0[NN * 8];     // tanh tables, layer 0 (fp16; 16B-aligned)
__device__ uint4  g_tth1[NN * 8];     // tanh tables, layer 1
__device__ float4 g_acc[NN * 16];     // running sum of layer embeddings (fp32)

// fp16x4 <-> float4 helpers
__device__ __forceinline__ float4 ld_h4(const uint2* p, int i) {
    uint2 u = __ldg(&p[i]);
    __half2 a = *reinterpret_cast<__half2*>(&u.x);
    __half2 b = *reinterpret_cast<__half2*>(&u.y);
    float2 fa = __half22float2(a), fb = __half22float2(b);
    return make_float4(fa.x, fa.y, fb.x, fb.y);
}
__device__ __forceinline__ uint2 st_h4(float4 v) {
    __half2 a = __floats2half2_rn(v.x, v.y);
    __half2 b = __floats2half2_rn(v.z, v.w);
    uint2 u;
    u.x = *reinterpret_cast<unsigned*>(&a);
    u.y = *reinterpret_cast<unsigned*>(&b);
    return u;
}

// dot of 16-float hf with 16 fp16 values packed in two uint4
__device__ __forceinline__ float dot16(const float* hf, uint4 ua, uint4 ub) {
    const __half2* pa = reinterpret_cast<const __half2*>(&ua);
    const __half2* pb = reinterpret_cast<const __half2*>(&ub);
    float p0 = 0.f, p1 = 0.f, p2 = 0.f, p3 = 0.f;
    #pragma unroll
    for (int k = 0; k < 4; k++) {
        float2 fa = __half22float2(pa[k]);
        float2 fb = __half22float2(pb[k]);
        p0 = fmaf(hf[2 * k + 0], fa.x, p0);
        p1 = fmaf(hf[2 * k + 1], fa.y, p1);
        p2 = fmaf(hf[8 + 2 * k + 0], fb.x, p2);
        p3 = fmaf(hf[8 + 2 * k + 1], fb.y, p3);
    }
    return (p0 + p1) + (p2 + p3);
}

// ---------------- CSR build ---------------------------------------------------
__global__ void k_zero_deg() {
    int i = blockIdx.x * blockDim.x + threadIdx.x;
    if (i < NN) g_deg[i] = 0;
}

__global__ void k_hist(const int* __restrict__ head) {
    int e = blockIdx.x * blockDim.x + threadIdx.x;
    if (e < NNZE) atomicAdd(&g_deg[head[e]], 1);
}

__global__ void k_scan() {
    const int T = 1024;
    const int CHUNK = (NN + T - 1) / T;
    __shared__ int ssum[T];
    int t = threadIdx.x;
    int beg = t * CHUNK;
    int end = min(beg + CHUNK, NN);
    int s = 0;
    for (int i = beg; i < end; i++) s += g_deg[i];
    ssum[t] = s;
    __syncthreads();
    for (int off = 1; off < T; off <<= 1) {
        int v = 0;
        if (t >= off) v = ssum[t - off];
        __syncthreads();
        if (t >= off) ssum[t] += v;
        __syncthreads();
    }
    int run = ssum[t] - s;
    for (int i = beg; i < end; i++) {
        g_rowptr[i] = run;
        g_cursor[i] = run;
        run += g_deg[i];
    }
    if (t == T - 1) g_rowptr[NN] = ssum[T - 1];
}

__global__ void k_scatter(const int* __restrict__ head, const int* __restrict__ tail) {
    int e = blockIdx.x * blockDim.x + threadIdx.x;
    if (e >= NNZE) return;
    int pos = atomicAdd(&g_cursor[head[e]], 1);
    g_tails[pos] = tail[e];
}

// ---------------- init: ego0(fp16), acc(fp32), tt0(fp16), d0 ------------------
__global__ void k_init(const float* __restrict__ user, const float* __restrict__ item) {
    int i = blockIdx.x * blockDim.x + threadIdx.x;   // NN*16 exact
    int n = i >> 4, c = i & 15;
    const float* src = (n < NUSER) ? (user + (size_t)n * 64 + c * 4)
                                   : (item + (size_t)(n - NUSER) * 64 + c * 4);
    float4 v = *reinterpret_cast<const float4*>(src);
    g_h0[i] = st_h4(v);
    g_acc[i] = v;
    float ss = v.x*v.x + v.y*v.y + v.z*v.z + v.w*v.w;
    ss += __shfl_xor_sync(0xffffffffu, ss, 1);
    ss += __shfl_xor_sync(0xffffffffu, ss, 2);
    float inv = 1.f / fmaxf(sqrtf(ss), EPSV);
    reinterpret_cast<uint2*>(g_tth0)[i] =
        st_h4(make_float4(tanhf(v.x*inv), tanhf(v.y*inv), tanhf(v.z*inv), tanhf(v.w*inv)));
    if (c < 4) {
        float s = 0.25f * (float)(g_rowptr[n + 1] - g_rowptr[n]);
        g_d0[n * 4 + c] = (s > 0.f) ? (1.f / sqrtf(fmaxf(s, EPSV))) : 0.f;
    }
}

// ---------------- whole routing iteration (16 lanes per node) -----------------
// loop1 lane map: fl=c&3, s=c>>2, chunk=fl*4+s  (factor-major)
// loop2 lane map: e4=c>>2 (edge slot), fl2=c&3  (edge-parallel)
// mode 0: write hn, scores    mode 1: + acc, tt1    mode 2: out only
__global__ void k_fused(int xsel, int dsel, int ttsel, int first, int mode,
                        float* __restrict__ out) {
    int gid = blockIdx.x * blockDim.x + threadIdx.x;   // NN*16 exact
    int g  = gid >> 4, c = gid & 15;
    int fl = c & 3, s = c >> 2;
    int chunk = fl * 4 + s;
    int idx = g * 16 + chunk;

    const uint2* xs = xsel ? g_h1 : g_h0;
    uint2*       hn = xsel ? g_h0 : g_h1;
    const float* dcur  = dsel ? g_d1 : g_d0;
    float*       dnext = dsel ? g_d0 : g_d1;
    const uint4* tt = ttsel ? g_tth1 : g_tth0;

    unsigned gmask = 0xFFFFu << (threadIdx.x & 16);   // 16-lane group

    int beg = g_rowptr[g], end = g_rowptr[g + 1];

    // ---- loop 1: h = l2norm(D A D x) per factor ----
    float ax = 0.f, ay = 0.f, az = 0.f, aw = 0.f;
    int j = beg;
    for (; j + 1 < end; j += 2) {
        int t0 = g_tails[j], t1 = g_tails[j + 1];
        float w0 = first ? 0.25f : g_vals[j * 4 + fl];
        float w1 = first ? 0.25f : g_vals[(j + 1) * 4 + fl];
        float s0 = w0 * dcur[t0 * 4 + fl];
        float s1 = w1 * dcur[t1 * 4 + fl];
        float4 x0 = ld_h4(xs, t0 * 16 + chunk);
        float4 x1 = ld_h4(xs, t1 * 16 + chunk);
        ax = fmaf(s0, x0.x, ax); ay = fmaf(s0, x0.y, ay);
        az = fmaf(s0, x0.z, az); aw = fmaf(s0, x0.w, aw);
        ax = fmaf(s1, x1.x, ax); ay = fmaf(s1, x1.y, ay);
        az = fmaf(s1, x1.z, az); aw = fmaf(s1, x1.w, aw);
    }
    if (j < end) {
        int t = g_tails[j];
        float w = first ? 0.25f : g_vals[j * 4 + fl];
        float sc = w * dcur[t * 4 + fl];
        float4 x = ld_h4(xs, t * 16 + chunk);
        ax = fmaf(sc, x.x, ax); ay = fmaf(sc, x.y, ay);
        az = fmaf(sc, x.z, az); aw = fmaf(sc, x.w, aw);
    }
    float dn = dcur[g * 4 + fl];
    float fx = dn * ax, fy = dn * ay, fz = dn * az, fw = dn * aw;
    float ss = fx*fx + fy*fy + fz*fz + fw*fw;
    ss += __shfl_xor_sync(gmask, ss, 4);        // reduce over subchunks
    ss += __shfl_xor_sync(gmask, ss, 8);
    float inv = 1.f / fmaxf(sqrtf(ss), EPSV);
    float4 h = make_float4(fx * inv, fy * inv, fz * inv, fw * inv);

    if (mode == 2) {
        float4 a = g_acc[idx];
        const float k = 1.f / 3.f;
        reinterpret_cast<float4*>(out)[idx] =
            make_float4((a.x + h.x) * k, (a.y + h.y) * k, (a.z + h.z) * k, (a.w + h.w) * k);
        return;
    }
    hn[idx] = st_h4(h);
    if (mode == 1) {
        float4 a = g_acc[idx];
        g_acc[idx] = make_float4(a.x + h.x, a.y + h.y, a.z + h.z, a.w + h.w);
        reinterpret_cast<uint2*>(g_tth1)[idx] =
            st_h4(make_float4(tanhf(h.x), tanhf(h.y), tanhf(h.z), tanhf(h.w)));
    }

    // ---- broadcast full factor-h into every lane (for lane's loop-2 factor) --
    // chunk m = fl2*4+sp is HELD by lane (m&3)*4 + (m>>2) = sp*4 + fl2
    float hf[16];
    int fl2 = c & 3;
    #pragma unroll
    for (int sp = 0; sp < 4; sp++) {
        int src = sp * 4 + fl2;                 // inverse of the loop-1 lane map
        hf[sp * 4 + 0] = __shfl_sync(gmask, h.x, src, 16);
        hf[sp * 4 + 1] = __shfl_sync(gmask, h.y, src, 16);
        hf[sp * 4 + 2] = __shfl_sync(gmask, h.z, src, 16);
        hf[sp * 4 + 3] = __shfl_sync(gmask, h.w, src, 16);
    }

    // ---- loop 2: 4 edges per iteration, dot in-lane, softmax across fl lanes --
    int e4 = c >> 2;
    int iters = (end - beg + 3) >> 2;
    float rs = 0.f;
    for (int it = 0; it < iters; it++) {
        int jj = beg + it * 4 + e4;
        bool valid = (jj < end);
        int t = valid ? g_tails[jj] : 0;
        const uint4* tp = tt + t * 8 + fl2 * 2;
        uint4 ua = __ldg(tp);
        uint4 ub = __ldg(tp + 1);
        float p = dot16(hf, ua, ub);
        float Aold = valid ? (first ? 1.f : g_A[jj * 4 + fl2]) : 0.f;
        float An = Aold + p;
        if (valid) g_A[jj * 4 + fl2] = An;
        float m = An;
        m = fmaxf(m, __shfl_xor_sync(gmask, m, 1));
        m = fmaxf(m, __shfl_xor_sync(gmask, m, 2));
        float e0 = __expf(An - m);
        float sm = e0;
        sm += __shfl_xor_sync(gmask, sm, 1);
        sm += __shfl_xor_sync(gmask, sm, 2);
        float v = e0 / sm;
        if (valid) {
            g_vals[jj * 4 + fl2] = v;
            rs += v;
        }
    }
    // rowsum: combine edge slots (lanes with same fl2, e4 = 0..3)
    rs += __shfl_xor_sync(gmask, rs, 4);
    rs += __shfl_xor_sync(gmask, rs, 8);
    if (e4 == 0) {
        dnext[g * 4 + fl2] = (rs > 0.f) ? (1.f / sqrtf(fmaxf(rs, EPSV))) : 0.f;
    }
}

// ---------------- launch -------------------------------------------------------
extern "C" void kernel_launch(void* const* d_in, const int* in_sizes, int n_in,
                              void* d_out, int out_size) {
    const float* user = (const float*)d_in[0];
    const float* item = (const float*)d_in[1];
    const int*   head = (const int*)d_in[2];
    const int*   tail = (const int*)d_in[3];
    float* out = (float*)d_out;

    const int TB = 256;
    const int gN   = (NN + TB - 1) / TB;
    const int gN16 = (NN * 16) / TB;        // exact
    const int gE   = (NNZE + TB - 1) / TB;

    // CSR build
    k_zero_deg<<<gN, TB>>>();
    k_hist<<<gE, TB>>>(head);
    k_scan<<<1, 1024>>>();
    k_scatter<<<gE, TB>>>(head, tail);

    // ego0 + acc + tt0 + first-iteration d (needs rowptr)
    k_init<<<gN16, TB>>>(user, item);

    //            xsel dsel ttsel first mode
    k_fused<<<gN16, TB>>>(0, 0, 0, 1, 0, out);   // layer0 iter1
    k_fused<<<gN16, TB>>>(0, 1, 0, 0, 1, out);   // layer0 iter2: acc+, tt1
    k_fused<<<gN16, TB>>>(1, 0, 1, 0, 0, out);   // layer1 iter1
    k_fused<<<gN16, TB>>>(1, 1, 1, 0, 2, out);   // layer1 iter2: out
}